// round 4
// baseline (speedup 1.0000x reference)
#include <cuda_runtime.h>
#include <math.h>

#define B_ 2
#define L_ 256
#define H_ 256
#define C_ 5
#define VOCAB 255   // 2*127 + 1 distinct clipped distances

// Scratch (no cudaMalloc allowed)
__device__ __align__(16) float g_Rt[VOCAB * H_];     // rel_term table @ Wh_w + Wh_b  [255, 256]
__device__ __align__(16) float g_A [B_ * L_ * H_];   // hs @ (We + Wd)
__device__ __align__(16) float g_Bv[B_ * L_ * H_];   // hs @ (Ws - Wd)

// ---------------------------------------------------------------------------
// Kernel 1: Rt[d,h] = sum_k table[d,k] * Wh_w[k,h] + Wh_b[h]
// table[d,k] = sin/cos(d / 10000^{(k&~1)/1024})
// ---------------------------------------------------------------------------
__global__ void relterm_kernel(const float* __restrict__ Wh_w,
                               const float* __restrict__ Wh_b) {
    __shared__ float tbl[4 * H_];
    int d = blockIdx.x;
    int h = threadIdx.x;
    for (int k = h; k < 4 * H_; k += H_) {
        int kk = k & ~1;
        double dv  = pow(10000.0, (double)kk / (double)(4 * H_));
        double ang = (double)d / dv;
        tbl[k] = (k & 1) ? (float)cos(ang) : (float)sin(ang);
    }
    __syncthreads();
    float acc = Wh_b[h];
    #pragma unroll 8
    for (int k = 0; k < 4 * H_; k++)
        acc = fmaf(tbl[k], Wh_w[k * H_ + h], acc);
    g_Rt[d * H_ + h] = acc;
}

// ---------------------------------------------------------------------------
// Kernel 2: A[r,h] = hs[r,:] @ (We+Wd),  Bv[r,h] = hs[r,:] @ (Ws-Wd)
// 4 rows per block to amortize weight reads.
// ---------------------------------------------------------------------------
__global__ void ab_kernel(const float* __restrict__ hs,
                          const float* __restrict__ Wh_w) {
    __shared__ float rows[4][H_];
    int rb = blockIdx.x * 4;
    int h  = threadIdx.x;
    #pragma unroll
    for (int r = 0; r < 4; r++)
        rows[r][h] = hs[(rb + r) * H_ + h];
    __syncthreads();
    float accA[4] = {0.f, 0.f, 0.f, 0.f};
    float accB[4] = {0.f, 0.f, 0.f, 0.f};
    #pragma unroll 4
    for (int k = 0; k < H_; k++) {
        float we = Wh_w[(0 * H_ + k) * H_ + h];
        float ws = Wh_w[(1 * H_ + k) * H_ + h];
        float wd = Wh_w[(2 * H_ + k) * H_ + h];
        float wa = we + wd;
        float wb = ws - wd;
        #pragma unroll
        for (int r = 0; r < 4; r++) {
            float v = rows[r][k];
            accA[r] = fmaf(v, wa, accA[r]);
            accB[r] = fmaf(v, wb, accB[r]);
        }
    }
    #pragma unroll
    for (int r = 0; r < 4; r++) {
        g_A [(rb + r) * H_ + h] = accA[r];
        g_Bv[(rb + r) * H_ + h] = accB[r];
    }
}

// ---------------------------------------------------------------------------
// Main fused kernel. Block = (b, i, j-tile of 64). GEMM M=64(j) N=256(h) K=256.
// Left operand L[j,k] = hs[b,j,k] * hs[b,i,k]; right = Wm (rows 768..1023 of Wh_w).
// Epilogue: + A[i] + Bv[j] + Rt[dist] -> tanh -> @Wo_w (C=5) reduced via shuffles.
// ---------------------------------------------------------------------------
#define BM  64
#define BK  16
#define LSS 68    // padded strides -> conflict-free float4 LDS, 16B-aligned rows
#define WSS 260

__global__ __launch_bounds__(256, 2)
void main_kernel(const float* __restrict__ hs,
                 const int*   __restrict__ mask,
                 const float* __restrict__ Wh_w,
                 const float* __restrict__ Wo_w,
                 const float* __restrict__ Wo_b,
                 float* __restrict__ out) {
    __shared__ __align__(16) float Ls[BK][LSS];
    __shared__ __align__(16) float Ws[BK][WSS];
    __shared__ __align__(16) float hi[H_];
    __shared__ float woS[H_ * C_];
    __shared__ float wobS[C_];

    const int jt  = blockIdx.x;
    const int i   = blockIdx.y;
    const int b   = blockIdx.z;
    const int tid = threadIdx.x;
    const int tx  = tid & 31;
    const int ty  = tid >> 5;
    const float* Wm = Wh_w + 3 * H_ * H_;
    const int jbase = jt * BM;

    hi[tid] = hs[(b * L_ + i) * H_ + tid];
    for (int t = tid; t < H_ * C_; t += 256) woS[t] = Wo_w[t];
    if (tid < C_) wobS[tid] = Wo_b[tid];
    __syncthreads();

    float acc[8][8];
    #pragma unroll
    for (int m = 0; m < 8; m++)
        #pragma unroll
        for (int n = 0; n < 8; n++) acc[m][n] = 0.f;

    const int lj  = tid & 63;          // Ls load: j index
    const int lkq = (tid >> 6) * 4;    // Ls load: k quad
    const int wk  = tid >> 4;          // Ws load: k row
    const int whq = (tid & 15) * 16;   // Ws load: h base

    for (int kk = 0; kk < H_; kk += BK) {
        // stage Ls[k][j] = hs[b, jbase+j, kk+k] * hi[kk+k] (transposed store)
        float4 v  = *(const float4*)&hs[(b * L_ + jbase + lj) * H_ + kk + lkq];
        float4 hv = *(const float4*)&hi[kk + lkq];
        Ls[lkq + 0][lj] = v.x * hv.x;
        Ls[lkq + 1][lj] = v.y * hv.y;
        Ls[lkq + 2][lj] = v.z * hv.z;
        Ls[lkq + 3][lj] = v.w * hv.w;

        // stage Ws[k][h] = Wm[kk+k, h]
        const float4* src = (const float4*)&Wm[(kk + wk) * H_ + whq];
        float4* dst = (float4*)&Ws[wk][whq];
        dst[0] = src[0]; dst[1] = src[1]; dst[2] = src[2]; dst[3] = src[3];
        __syncthreads();

        #pragma unroll
        for (int k = 0; k < BK; k++) {
            float4 a0 = *(const float4*)&Ls[k][ty * 4];
            float4 a1 = *(const float4*)&Ls[k][32 + ty * 4];
            float4 b0 = *(const float4*)&Ws[k][tx * 4];
            float4 b1 = *(const float4*)&Ws[k][128 + tx * 4];
            float am[8] = {a0.x, a0.y, a0.z, a0.w, a1.x, a1.y, a1.z, a1.w};
            float bn[8] = {b0.x, b0.y, b0.z, b0.w, b1.x, b1.y, b1.z, b1.w};
            #pragma unroll
            for (int m = 0; m < 8; m++)
                #pragma unroll
                for (int n = 0; n < 8; n++)
                    acc[m][n] = fmaf(am[m], bn[n], acc[m][n]);
        }
        __syncthreads();
    }

    // ---- fused epilogue ----
    const int hseg0 = tx * 4, hseg1 = 128 + tx * 4;
    const float* Arow = &g_A[(b * L_ + i) * H_];
    float4 A0 = *(const float4*)&Arow[hseg0];
    float4 A1 = *(const float4*)&Arow[hseg1];
    float ai[8] = {A0.x, A0.y, A0.z, A0.w, A1.x, A1.y, A1.z, A1.w};

    float part[8][C_];
    #pragma unroll
    for (int m = 0; m < 8; m++)
        #pragma unroll
        for (int c = 0; c < C_; c++) part[m][c] = 0.f;

    #pragma unroll
    for (int m = 0; m < 8; m++) {
        int j = jbase + ((m < 4) ? (ty * 4 + m) : (32 + ty * 4 + m - 4));
        int dd = j - i;
        dd = dd < -127 ? -127 : (dd > 127 ? 127 : dd);
        int d = dd + 127;
        float4 Bq0 = *(const float4*)&g_Bv[(b * L_ + j) * H_ + hseg0];
        float4 Bq1 = *(const float4*)&g_Bv[(b * L_ + j) * H_ + hseg1];
        float4 R0  = *(const float4*)&g_Rt[d * H_ + hseg0];
        float4 R1  = *(const float4*)&g_Rt[d * H_ + hseg1];
        float bj[8] = {Bq0.x, Bq0.y, Bq0.z, Bq0.w, Bq1.x, Bq1.y, Bq1.z, Bq1.w};
        float rj[8] = {R0.x,  R0.y,  R0.z,  R0.w,  R1.x,  R1.y,  R1.z,  R1.w};
        #pragma unroll
        for (int n = 0; n < 8; n++) {
            float pre = acc[m][n] + ai[n] + bj[n] + rj[n];
            float t = tanhf(pre);
            int hn = (n < 4) ? (hseg0 + n) : (hseg1 + n - 4);
            const float* wo = &woS[hn * C_];
            #pragma unroll
            for (int c = 0; c < C_; c++)
                part[m][c] = fmaf(t, wo[c], part[m][c]);
        }
    }

    // reduce across the 32 lanes (h dimension) of each warp
    #pragma unroll
    for (int m = 0; m < 8; m++)
        #pragma unroll
        for (int c = 0; c < C_; c++) {
            float vsum = part[m][c];
            #pragma unroll
            for (int s = 16; s > 0; s >>= 1)
                vsum += __shfl_xor_sync(0xffffffffu, vsum, s);
            part[m][c] = vsum;
        }

    if (tx == 0) {
        int mi = mask[b * L_ + i];
        #pragma unroll
        for (int m = 0; m < 8; m++) {
            int j = jbase + ((m < 4) ? (ty * 4 + m) : (32 + ty * 4 + m - 4));
            int mj = mask[b * L_ + j];
            #pragma unroll
            for (int c = 0; c < C_; c++) {
                float v = part[m][c] + wobS[c];
                if (!mi || !mj) v = -INFINITY;
                if (i > j) v -= 1e12f;
                out[((b * C_ + c) * L_ + i) * L_ + j] = v;
            }
        }
    }
}

// ---------------------------------------------------------------------------
extern "C" void kernel_launch(void* const* d_in, const int* in_sizes, int n_in,
                              void* d_out, int out_size) {
    const float* hs   = (const float*)d_in[0];
    const int*   mask = (const int*)  d_in[1];
    const float* Wh_w = (const float*)d_in[2];
    const float* Wh_b = (const float*)d_in[3];
    const float* Wo_w = (const float*)d_in[4];
    const float* Wo_b = (const float*)d_in[5];
    float* out = (float*)d_out;

    relterm_kernel<<<VOCAB, H_>>>(Wh_w, Wh_b);
    ab_kernel<<<(B_ * L_) / 4, H_>>>(hs, Wh_w);
    dim3 grid(L_ / BM, L_, B_);
    main_kernel<<<grid, 256>>>(hs, mask, Wh_w, Wo_w, Wo_b, out);
}

// round 8
// speedup vs baseline: 3.2009x; 3.2009x over previous
#include <cuda_runtime.h>
#include <cuda_bf16.h>
#include <math.h>
#include <cstdint>

#define B_ 2
#define L_ 256
#define H_ 256
#define C_ 5
#define VOCAB 255   // 2*127 + 1 distinct clipped distances

// ---- scratch (no cudaMalloc allowed) ----
__device__ __align__(16) float g_Rt[VOCAB * H_];            // table@Wh_w + Wh_b   [255,256]
__device__ __align__(16) float g_A [B_ * L_ * H_];          // hs @ (We + Wd)
__device__ __align__(16) __nv_bfloat16 g_hsb[B_ * L_ * H_]; // bf16 hidden_state
__device__ __align__(16) __nv_bfloat16 g_Wm [H_ * H_];      // bf16 Wm
__device__ __align__(16) __nv_bfloat16 g_Wb [H_ * H_];      // bf16 (Ws - Wd)

// ---------------------------------------------------------------------------
// prep: bf16 conversions
// ---------------------------------------------------------------------------
__global__ void prep_kernel(const float* __restrict__ hs,
                            const float* __restrict__ Wh_w) {
    int idx = blockIdx.x * 256 + threadIdx.x;
    if (idx < B_ * L_ * H_)
        g_hsb[idx] = __float2bfloat16(hs[idx]);
    int r = idx - B_ * L_ * H_;
    if (r >= 0 && r < H_ * H_)
        g_Wm[r] = __float2bfloat16(Wh_w[3 * H_ * H_ + r]);
    int r2 = r - H_ * H_;
    if (r2 >= 0 && r2 < H_ * H_)
        g_Wb[r2] = __float2bfloat16(Wh_w[1 * H_ * H_ + r2] - Wh_w[2 * H_ * H_ + r2]);
}

// ---------------------------------------------------------------------------
// relterm (fp32): Rt[d,h] = sum_k table[d,k]*Wh_w[k,h] + Wh_b[h]
// 3 distance rows per block (255 = 85*3) to amortize the 1MB Wh_w read.
// ---------------------------------------------------------------------------
__global__ void relterm_kernel(const float* __restrict__ Wh_w,
                               const float* __restrict__ Wh_b) {
    __shared__ float tbl[3][4 * H_];
    const int d0 = blockIdx.x * 3;
    const int h  = threadIdx.x;
    const float cst = -logf(10000.0f) / (float)(4 * H_);
    for (int k = h; k < 4 * H_; k += H_) {
        int kk = k & ~1;
        float w = expf(cst * (float)kk);
        #pragma unroll
        for (int r = 0; r < 3; r++) {
            float ang = (float)(d0 + r) * w;
            tbl[r][k] = (k & 1) ? cosf(ang) : sinf(ang);
        }
    }
    __syncthreads();
    float a0 = Wh_b[h], a1 = a0, a2 = a0;
    #pragma unroll 4
    for (int k = 0; k < 4 * H_; k++) {
        float wv = Wh_w[k * H_ + h];
        a0 = fmaf(tbl[0][k], wv, a0);
        a1 = fmaf(tbl[1][k], wv, a1);
        a2 = fmaf(tbl[2][k], wv, a2);
    }
    g_Rt[(d0 + 0) * H_ + h] = a0;
    g_Rt[(d0 + 1) * H_ + h] = a1;
    g_Rt[(d0 + 2) * H_ + h] = a2;
}

// ---------------------------------------------------------------------------
// A[r,h] = hs[r,:] @ (We + Wd)     (Bv folded into the main GEMM now)
// ---------------------------------------------------------------------------
__global__ void a_kernel(const float* __restrict__ hs,
                         const float* __restrict__ Wh_w) {
    __shared__ float rows[4][H_];
    int rb = blockIdx.x * 4;
    int h  = threadIdx.x;
    #pragma unroll
    for (int r = 0; r < 4; r++)
        rows[r][h] = hs[(rb + r) * H_ + h];
    __syncthreads();
    float acc[4] = {0.f, 0.f, 0.f, 0.f};
    #pragma unroll 4
    for (int k = 0; k < H_; k++) {
        float wa = Wh_w[k * H_ + h] + Wh_w[(2 * H_ + k) * H_ + h];
        #pragma unroll
        for (int r = 0; r < 4; r++)
            acc[r] = fmaf(rows[r][k], wa, acc[r]);
    }
    #pragma unroll
    for (int r = 0; r < 4; r++)
        g_A[(rb + r) * H_ + h] = acc[r];
}

// ---------------------------------------------------------------------------
// main: per block (b, i, j-tile of 128). bf16 mma.sync GEMM M=128 N=256 K=256
//   pre[j,h] = sum_k hsb[j,k]*(hi[k]*Wm[k,h] + Wb[k,h]) + A_i[h] + Rt[d(j,i)][h]
//   out = tanh(pre) @ Wo + Wo_b  (C=5 reduced via quad-shuffle + smem atomics)
// ---------------------------------------------------------------------------
#define BM 128
#define BK 32
#define SA 40     // As stride (bf16): 80B rows, conflict-free ldmatrix
#define SB 264    // Bs stride (bf16): 528B rows, 4-bank shift -> conflict-free
#define NT 512

__device__ __forceinline__ float tanha(float x) {
    float r; asm("tanh.approx.f32 %0, %1;" : "=f"(r) : "f"(x)); return r;
}
__device__ __forceinline__ void ldsm4(unsigned r[4], uint32_t a) {
    asm volatile("ldmatrix.sync.aligned.m8n8.x4.shared.b16 {%0,%1,%2,%3}, [%4];"
                 : "=r"(r[0]), "=r"(r[1]), "=r"(r[2]), "=r"(r[3]) : "r"(a));
}
__device__ __forceinline__ void ldsm4t(unsigned r[4], uint32_t a) {
    asm volatile("ldmatrix.sync.aligned.m8n8.x4.trans.shared.b16 {%0,%1,%2,%3}, [%4];"
                 : "=r"(r[0]), "=r"(r[1]), "=r"(r[2]), "=r"(r[3]) : "r"(a));
}
__device__ __forceinline__ void mma16816(float d[4], const unsigned a[4], const unsigned b[2]) {
    asm volatile("mma.sync.aligned.m16n8k16.row.col.f32.bf16.bf16.f32 "
                 "{%0,%1,%2,%3}, {%4,%5,%6,%7}, {%8,%9}, {%0,%1,%2,%3};"
                 : "+f"(d[0]), "+f"(d[1]), "+f"(d[2]), "+f"(d[3])
                 : "r"(a[0]), "r"(a[1]), "r"(a[2]), "r"(a[3]), "r"(b[0]), "r"(b[1]));
}

__global__ __launch_bounds__(NT, 1)
void main_kernel(const int*   __restrict__ mask,
                 const float* __restrict__ Wo_w,
                 const float* __restrict__ Wo_b,
                 float* __restrict__ out) {
    __shared__ __align__(16) __nv_bfloat16 As[BM * SA];
    __shared__ __align__(16) __nv_bfloat16 Bs[BK * SB];
    __shared__ __align__(16) __nv_bfloat16 hibS[H_];
    __shared__ __align__(16) float aiS[H_];
    __shared__ __align__(16) float woS[H_ * 8];
    __shared__ float wobS[8];
    __shared__ float red[BM * C_];

    const int jt = blockIdx.x, i = blockIdx.y, b = blockIdx.z;
    const int jbase = jt * BM;
    const int tid  = threadIdx.x;
    const int lane = tid & 31, warp = tid >> 5;
    const int wm = warp >> 2, wn = warp & 3;   // warp tile: m = wm*32 (4), n = wn*64 (4)

    // ---- preload ----
    if (tid < H_) {
        hibS[tid] = g_hsb[(b * L_ + i) * H_ + tid];
        aiS[tid]  = g_A[(b * L_ + i) * H_ + tid];
    }
    for (int t = tid; t < H_ * C_; t += NT)
        woS[(t / C_) * 8 + (t % C_)] = Wo_w[t];
    if (tid < C_) wobS[tid] = Wo_b[tid];
    for (int t = tid; t < BM * C_; t += NT) red[t] = 0.f;
    __syncthreads();

    float acc[2][8][4];
    #pragma unroll
    for (int mt = 0; mt < 2; mt++)
        #pragma unroll
        for (int nt = 0; nt < 8; nt++)
            #pragma unroll
            for (int q = 0; q < 4; q++) acc[mt][nt][q] = 0.f;

    const int sj = tid >> 2, sk = (tid & 3) * 8;      // As staging: 1 uint4/thread
    const int bk = tid >> 4, bn = (tid & 15) * 16;    // Bs staging: 16 el/thread
    const uint32_t AsA = (uint32_t)__cvta_generic_to_shared(As);
    const uint32_t BsA = (uint32_t)__cvta_generic_to_shared(Bs);
    const __nv_bfloat16* hsrow = g_hsb + (b * L_ + jbase) * H_;

    const int g  = lane >> 3, r8 = lane & 7;
    const int arow = ((g & 1) << 3) + r8;
    const int acolg = (g >> 1) << 3;
    const int browg = ((g & 1) << 3) + r8;
    const int bcol  = (g >> 1) << 3;

    for (int kk = 0; kk < H_; kk += BK) {
        // stage As[j][k] = hsb[j, kk+k]  (pure copy, bf16)
        *(uint4*)&As[sj * SA + sk] = *(const uint4*)&hsrow[sj * H_ + kk + sk];
        // stage Bs[k][h] = hi[kk+k]*Wm[kk+k,h] + Wb[kk+k,h]  (HFMA2)
        {
            __nv_bfloat162 h2 = __bfloat162bfloat162(hibS[kk + bk]);
            const __nv_bfloat162* wmp = (const __nv_bfloat162*)&g_Wm[(kk + bk) * H_ + bn];
            const __nv_bfloat162* wbp = (const __nv_bfloat162*)&g_Wb[(kk + bk) * H_ + bn];
            __nv_bfloat162* dst = (__nv_bfloat162*)&Bs[bk * SB + bn];
            #pragma unroll
            for (int q = 0; q < 8; q++)
                dst[q] = __hfma2(h2, wmp[q], wbp[q]);
        }
        __syncthreads();

        #pragma unroll
        for (int ks = 0; ks < BK; ks += 16) {
            unsigned af[2][4], bfr[8][2];
            #pragma unroll
            for (int mt = 0; mt < 2; mt++)
                ldsm4(af[mt], AsA + (((wm * 32 + mt * 16 + arow) * SA + ks + acolg) << 1));
            #pragma unroll
            for (int p = 0; p < 4; p++) {
                unsigned q[4];
                ldsm4t(q, BsA + (((ks + browg) * SB + wn * 64 + p * 16 + bcol) << 1));
                bfr[2 * p][0] = q[0]; bfr[2 * p][1] = q[1];
                bfr[2 * p + 1][0] = q[2]; bfr[2 * p + 1][1] = q[3];
            }
            #pragma unroll
            for (int mt = 0; mt < 2; mt++)
                #pragma unroll
                for (int nt = 0; nt < 8; nt++)
                    mma16816(acc[mt][nt], af[mt], bfr[nt]);
        }
        __syncthreads();
    }

    // ---- fused epilogue ----
    float ps[4][C_];
    #pragma unroll
    for (int ri = 0; ri < 4; ri++)
        #pragma unroll
        for (int cc = 0; cc < C_; cc++) ps[ri][cc] = 0.f;

    const int rb = lane >> 2, qc = (lane & 3) * 2;
    #pragma unroll
    for (int nt = 0; nt < 8; nt++) {
        int c = wn * 64 + nt * 8 + qc;
        float ai0 = aiS[c], ai1 = aiS[c + 1];
        float4 wv0 = *(const float4*)&woS[c * 8];
        float  w04 = woS[c * 8 + 4];
        float4 wv1 = *(const float4*)&woS[(c + 1) * 8];
        float  w14 = woS[(c + 1) * 8 + 4];
        float w0[5] = {wv0.x, wv0.y, wv0.z, wv0.w, w04};
        float w1[5] = {wv1.x, wv1.y, wv1.z, wv1.w, w14};
        #pragma unroll
        for (int mt = 0; mt < 2; mt++) {
            int r0 = wm * 32 + mt * 16 + rb;
            int r1 = r0 + 8;
            int j0 = jbase + r0, j1 = jbase + r1;
            int d0 = min(max(j0 - i, -127), 127) + 127;
            int d1 = min(max(j1 - i, -127), 127) + 127;
            float2 R0 = *(const float2*)&g_Rt[d0 * H_ + c];
            float2 R1 = *(const float2*)&g_Rt[d1 * H_ + c];
            const float* a4 = acc[mt][nt];
            float t00 = tanha(a4[0] + ai0 + R0.x);
            float t01 = tanha(a4[1] + ai1 + R0.y);
            float t10 = tanha(a4[2] + ai0 + R1.x);
            float t11 = tanha(a4[3] + ai1 + R1.y);
            #pragma unroll
            for (int cc = 0; cc < C_; cc++) {
                ps[2 * mt][cc]     = fmaf(t00, w0[cc], fmaf(t01, w1[cc], ps[2 * mt][cc]));
                ps[2 * mt + 1][cc] = fmaf(t10, w0[cc], fmaf(t11, w1[cc], ps[2 * mt + 1][cc]));
            }
        }
    }

    // quad-reduce (cols within quad are disjoint) then smem atomic across n-warps
    #pragma unroll
    for (int ri = 0; ri < 4; ri++) {
        int row = wm * 32 + (ri >> 1) * 16 + (ri & 1) * 8 + rb;
        #pragma unroll
        for (int cc = 0; cc < C_; cc++) {
            float v = ps[ri][cc];
            v += __shfl_xor_sync(0xffffffffu, v, 1);
            v += __shfl_xor_sync(0xffffffffu, v, 2);
            if ((lane & 3) == 0) atomicAdd(&red[row * C_ + cc], v);
        }
    }
    __syncthreads();

    if (tid < BM) {
        int j  = jbase + tid;
        int mi = mask[b * L_ + i];
        int mj = mask[b * L_ + j];
        bool bad = (!mi) || (!mj);
        #pragma unroll
        for (int cc = 0; cc < C_; cc++) {
            float v = red[tid * C_ + cc] + wobS[cc];
            if (bad) v = -INFINITY;
            if (i > j) v -= 1e12f;
            out[((b * C_ + cc) * L_ + i) * L_ + j] = v;
        }
    }
}

// ---------------------------------------------------------------------------
extern "C" void kernel_launch(void* const* d_in, const int* in_sizes, int n_in,
                              void* d_out, int out_size) {
    const float* hs   = (const float*)d_in[0];
    const int*   mask = (const int*)  d_in[1];
    const float* Wh_w = (const float*)d_in[2];
    const float* Wh_b = (const float*)d_in[3];
    const float* Wo_w = (const float*)d_in[4];
    const float* Wo_b = (const float*)d_in[5];
    float* out = (float*)d_out;

    prep_kernel<<<(B_ * L_ * H_ + 2 * H_ * H_) / 256, 256>>>(hs, Wh_w);
    relterm_kernel<<<85, H_>>>(Wh_w, Wh_b);
    a_kernel<<<(B_ * L_) / 4, H_>>>(hs, Wh_w);
    dim3 grid(L_ / BM, L_, B_);
    main_kernel<<<grid, NT>>>(mask, Wo_w, Wo_b, out);
}